// round 6
// baseline (speedup 1.0000x reference)
#include <cuda_runtime.h>
#include <cuda_bf16.h>
#include <math.h>

// Problem constants
#define NQ      6400
#define CDIM    128
#define SCAM    6
#define MPIX    2816     // 32*88
#define HEADS   4
#define POINTS  20
#define HSZ     32
#define WSZ     88
#define DHEAD   32
#define DANCH   4
#define OFF_W   160      // HEADS*POINTS*2
#define ATTN_W  80       // HEADS*POINTS
#define NCOMB   240      // OFF_W + ATTN_W

#define TMB     64       // rows per block: kernels A and B
#define TMD     32       // rows per block: kernel D

// Scratch (device globals -- no allocation allowed)
__device__ float         g_off[NQ * OFF_W];              // sampling offsets, already /norm
__device__ float         g_aw [NQ * ATTN_W];             // softmaxed attention weights
__device__ __nv_bfloat16 g_val[SCAM * MPIX * CDIM];      // projected value, (s,pix,c) bf16
__device__ float         g_slots[NQ * CDIM];             // per-query accumulated slots

// Aux stream for A||B overlap -- created once in a static initializer (before
// main; no per-call guards, no device memory).
namespace {
struct AuxStream {
    cudaStream_t s;
    cudaEvent_t evFork, evJoin;
    AuxStream() {
        cudaStreamCreateWithFlags(&s, cudaStreamNonBlocking);
        cudaEventCreateWithFlags(&evFork, cudaEventDisableTiming);
        cudaEventCreateWithFlags(&evJoin, cudaEventDisableTiming);
    }
};
AuxStream g_aux;
}

// ---------------------------------------------------------------------------
// Kernel A: q = query+query_pos; [offsets | attn logits] = q @ [Woff|Wattn]
// 512 threads, 64 rows x 240 cols, micro-tile 2 rows x 15 cols.
// ---------------------------------------------------------------------------
__global__ void __launch_bounds__(512)
k_proj_off_attn_t(const float* __restrict__ query,
                  const float* __restrict__ qpos,
                  const float* __restrict__ Woff,
                  const float* __restrict__ boff,
                  const float* __restrict__ Wattn,
                  const float* __restrict__ battn) {
    extern __shared__ float smem[];
    float* sW = smem;                 // [128][240]
    float* sA = smem + 128 * NCOMB;   // [64][128]

    const int n0  = blockIdx.x * TMB;
    const int tid = threadIdx.x;

    for (int idx = tid; idx < 128 * NCOMB; idx += 512) {
        const int k = idx / NCOMB, n = idx - k * NCOMB;
        sW[idx] = (n < OFF_W) ? Woff[k * OFF_W + n] : Wattn[k * ATTN_W + (n - OFF_W)];
    }
    for (int idx = tid; idx < TMB * 128; idx += 512) {
        const int g = n0 * CDIM + idx;
        sA[idx] = query[g] + qpos[g];
    }
    __syncthreads();

    const int tx = tid & 15;          // col group: cols tx + 16*j
    const int ry = tid >> 4;          // 0..31 -> rows 2*ry, 2*ry+1
    const int r0 = ry * 2, r1 = r0 + 1;

    float acc[2][15];
    #pragma unroll
    for (int i = 0; i < 2; i++)
        #pragma unroll
        for (int j = 0; j < 15; j++) acc[i][j] = 0.f;

    for (int k4 = 0; k4 < 128; k4 += 4) {
        const float4 a0 = *reinterpret_cast<const float4*>(&sA[r0 * 128 + k4]);
        const float4 a1 = *reinterpret_cast<const float4*>(&sA[r1 * 128 + k4]);
        #pragma unroll
        for (int kk = 0; kk < 4; kk++) {
            const float ak0 = (&a0.x)[kk];
            const float ak1 = (&a1.x)[kk];
            #pragma unroll
            for (int j = 0; j < 15; j++) {
                const float w = sW[(k4 + kk) * NCOMB + tx + 16 * j];
                acc[0][j] = fmaf(ak0, w, acc[0][j]);
                acc[1][j] = fmaf(ak1, w, acc[1][j]);
            }
        }
    }
    __syncthreads();

    #pragma unroll
    for (int i = 0; i < 2; i++)
        #pragma unroll
        for (int j = 0; j < 15; j++)
            sW[(r0 + i) * NCOMB + tx + 16 * j] = acc[i][j];
    __syncthreads();

    for (int idx = tid; idx < TMB * OFF_W; idx += 512) {
        const int r = idx / OFF_W, t = idx - r * OFF_W;
        const float v = sW[r * NCOMB + t] + boff[t];
        g_off[(n0 + r) * OFF_W + t] = v * ((t & 1) ? (1.f / 32.f) : (1.f / 88.f));
    }
    if (tid < 256) {
        const int r = tid >> 2, h = tid & 3;
        float lg[POINTS];
        float mx = -1e30f;
        #pragma unroll
        for (int p = 0; p < POINTS; p++) {
            lg[p] = sW[r * NCOMB + OFF_W + h * POINTS + p] + battn[h * POINTS + p];
            mx = fmaxf(mx, lg[p]);
        }
        float sum = 0.f;
        #pragma unroll
        for (int p = 0; p < POINTS; p++) { lg[p] = __expf(lg[p] - mx); sum += lg[p]; }
        const float inv = 1.f / sum;
        #pragma unroll
        for (int p = 0; p < POINTS; p++)
            g_aw[(n0 + r) * ATTN_W + h * POINTS + p] = lg[p] * inv;
    }
}

// ---------------------------------------------------------------------------
// Kernel B: val = value @ Wv + bv -> bf16 (s,pix,c).
// 512 threads, 64 rows, micro-tile 2 rows x 8 cols; lane L and L+16 share the
// weight column group -> weight LDS.128 dedups to 16 unique addrs/warp.
// ---------------------------------------------------------------------------
__global__ void __launch_bounds__(512)
k_proj_val_t(const float* __restrict__ value,
             const float* __restrict__ Wv,
             const float* __restrict__ bv) {
    extern __shared__ float smem[];
    float* sW = smem;                 // [128][128]
    float* sA = smem + 128 * 128;     // [64][128]

    const int n0  = blockIdx.x * TMB;
    const int tid = threadIdx.x;

    for (int idx = tid; idx < 128 * 128 / 4; idx += 512)
        reinterpret_cast<float4*>(sW)[idx] = reinterpret_cast<const float4*>(Wv)[idx];
    for (int idx = tid; idx < TMB * 128 / 4; idx += 512)
        reinterpret_cast<float4*>(sA)[idx] =
            reinterpret_cast<const float4*>(value + (size_t)n0 * CDIM)[idx];
    __syncthreads();

    const int tx = tid & 15;
    const int ry = tid >> 4;          // 0..31
    const int r0 = ry * 2, r1 = r0 + 1;

    float acc[2][8];
    #pragma unroll
    for (int i = 0; i < 2; i++)
        #pragma unroll
        for (int j = 0; j < 8; j++) acc[i][j] = 0.f;

    for (int k4 = 0; k4 < 128; k4 += 4) {
        const float4 a0 = *reinterpret_cast<const float4*>(&sA[r0 * 128 + k4]);
        const float4 a1 = *reinterpret_cast<const float4*>(&sA[r1 * 128 + k4]);
        #pragma unroll
        for (int kk = 0; kk < 4; kk++) {
            const float ak0 = (&a0.x)[kk];
            const float ak1 = (&a1.x)[kk];
            const float4 w0 = *reinterpret_cast<const float4*>(&sW[(k4 + kk) * 128 + tx * 8]);
            const float4 w1 = *reinterpret_cast<const float4*>(&sW[(k4 + kk) * 128 + tx * 8 + 4]);
            acc[0][0] = fmaf(ak0, w0.x, acc[0][0]); acc[1][0] = fmaf(ak1, w0.x, acc[1][0]);
            acc[0][1] = fmaf(ak0, w0.y, acc[0][1]); acc[1][1] = fmaf(ak1, w0.y, acc[1][1]);
            acc[0][2] = fmaf(ak0, w0.z, acc[0][2]); acc[1][2] = fmaf(ak1, w0.z, acc[1][2]);
            acc[0][3] = fmaf(ak0, w0.w, acc[0][3]); acc[1][3] = fmaf(ak1, w0.w, acc[1][3]);
            acc[0][4] = fmaf(ak0, w1.x, acc[0][4]); acc[1][4] = fmaf(ak1, w1.x, acc[1][4]);
            acc[0][5] = fmaf(ak0, w1.y, acc[0][5]); acc[1][5] = fmaf(ak1, w1.y, acc[1][5]);
            acc[0][6] = fmaf(ak0, w1.z, acc[0][6]); acc[1][6] = fmaf(ak1, w1.z, acc[1][6]);
            acc[0][7] = fmaf(ak0, w1.w, acc[0][7]); acc[1][7] = fmaf(ak1, w1.w, acc[1][7]);
        }
    }

    const float4 b0 = *reinterpret_cast<const float4*>(&bv[tx * 8]);
    const float4 b1 = *reinterpret_cast<const float4*>(&bv[tx * 8 + 4]);
    #pragma unroll
    for (int i = 0; i < 2; i++) {
        const int row = n0 + r0 + i;
        __nv_bfloat162 h0 = __floats2bfloat162_rn(acc[i][0] + b0.x, acc[i][1] + b0.y);
        __nv_bfloat162 h1 = __floats2bfloat162_rn(acc[i][2] + b0.z, acc[i][3] + b0.w);
        __nv_bfloat162 h2 = __floats2bfloat162_rn(acc[i][4] + b1.x, acc[i][5] + b1.y);
        __nv_bfloat162 h3 = __floats2bfloat162_rn(acc[i][6] + b1.z, acc[i][7] + b1.w);
        uint4 u;
        u.x = *reinterpret_cast<unsigned*>(&h0);
        u.y = *reinterpret_cast<unsigned*>(&h1);
        u.z = *reinterpret_cast<unsigned*>(&h2);
        u.w = *reinterpret_cast<unsigned*>(&h3);
        *reinterpret_cast<uint4*>(&g_val[(size_t)row * CDIM + tx * 8]) = u;
    }
}

// ---------------------------------------------------------------------------
// Kernel C: bilinear sampling. Block = query (128 threads), warp = head.
// lane = (half<<4) | (corner<<2) | chgrp; 2 points x 4 corners x 32 channels
// per warp iteration, one LDG.128 per lane. Offsets/attn-weights hoisted to
// registers; ref points selected from two register pairs (d alternates).
// Butterfly reduction (xor 4, 8, 16) at the end.
// ---------------------------------------------------------------------------
__global__ void k_sample(const float* __restrict__ refpts,   // (S,1,N,4,2)
                         const int* __restrict__ bmask) {    // (S,1,N,4) 4-byte flags
    const int n    = blockIdx.x;
    const int t    = threadIdx.x;
    const int h    = t >> 5;
    const int lane = t & 31;
    const int half = lane >> 4;        // which point of the pair
    const int c2   = (lane >> 2) & 3;  // bilinear corner
    const int dx   = c2 & 1, dy = c2 >> 1;
    const int g2   = lane & 3;         // channel group of 8

    __shared__ float sOff[OFF_W];
    __shared__ float sAw[ATTN_W];
    __shared__ float sRef[SCAM * 8];
    __shared__ int   sAct[SCAM];
    __shared__ int   sCnt;

    for (int i = t; i < OFF_W; i += 128)  sOff[i] = g_off[n * OFF_W + i];
    for (int i = t; i < ATTN_W; i += 128) sAw[i]  = g_aw[n * ATTN_W + i];
    for (int i = t; i < SCAM * 8; i += 128) {
        const int s = i >> 3, e = i & 7;
        sRef[i] = refpts[((size_t)s * NQ + n) * 8 + e];
    }
    if (t == 0) {
        int cnt = 0;
        #pragma unroll
        for (int s = 0; s < SCAM; s++) {
            const int4 mw = *reinterpret_cast<const int4*>(bmask + ((size_t)s * NQ + n) * DANCH);
            if (mw.x | mw.y | mw.z | mw.w) sAct[cnt++] = s;
        }
        sCnt = cnt;
    }
    __syncthreads();

    // hoist this lane's 10 points: offsets and attention weights
    float ox[10], oy[10], wp[10];
    #pragma unroll
    for (int i = 0; i < 10; i++) {
        const int p = 2 * i + half;
        ox[i] = sOff[h * 40 + p * 2 + 0];
        oy[i] = sOff[h * 40 + p * 2 + 1];
        wp[i] = sAw[h * POINTS + p];
    }

    float acc[8];
    #pragma unroll
    for (int i = 0; i < 8; i++) acc[i] = 0.f;

    const int cnt = sCnt;
    for (int j = 0; j < cnt; j++) {
        const int s = sAct[j];
        const __nv_bfloat16* __restrict__ imgb =
            g_val + (size_t)s * MPIX * CDIM + h * DHEAD + g2 * 8;
        const float* __restrict__ rf = &sRef[s * 8];
        // anchor d = half for even i, 2+half for odd i
        const float fx0 = rf[half * 2 + 0], fy0 = rf[half * 2 + 1];
        const float fx2 = rf[half * 2 + 4], fy2 = rf[half * 2 + 5];

        #pragma unroll
        for (int i = 0; i < 10; i++) {
            const float bx = (i & 1) ? fx2 : fx0;
            const float by = (i & 1) ? fy2 : fy0;
            const float x = (bx + ox[i]) * 88.f - 0.5f;
            const float y = (by + oy[i]) * 32.f - 0.5f;
            const float x0f = floorf(x), y0f = floorf(y);
            const float wx = x - x0f, wy = y - y0f;
            const int xx = (int)x0f + dx;
            const int yy = (int)y0f + dy;
            const float wc = (dx ? wx : 1.f - wx) * (dy ? wy : 1.f - wy) * wp[i];

            if ((unsigned)xx < (unsigned)WSZ && (unsigned)yy < (unsigned)HSZ) {
                const uint4 raw = *reinterpret_cast<const uint4*>(imgb + (yy * WSZ + xx) * CDIM);
                const float2 f0 = __bfloat1622float2(*reinterpret_cast<const __nv_bfloat162*>(&raw.x));
                const float2 f1 = __bfloat1622float2(*reinterpret_cast<const __nv_bfloat162*>(&raw.y));
                const float2 f2 = __bfloat1622float2(*reinterpret_cast<const __nv_bfloat162*>(&raw.z));
                const float2 f3 = __bfloat1622float2(*reinterpret_cast<const __nv_bfloat162*>(&raw.w));
                acc[0] = fmaf(wc, f0.x, acc[0]);
                acc[1] = fmaf(wc, f0.y, acc[1]);
                acc[2] = fmaf(wc, f1.x, acc[2]);
                acc[3] = fmaf(wc, f1.y, acc[3]);
                acc[4] = fmaf(wc, f2.x, acc[4]);
                acc[5] = fmaf(wc, f2.y, acc[5]);
                acc[6] = fmaf(wc, f3.x, acc[6]);
                acc[7] = fmaf(wc, f3.y, acc[7]);
            }
        }
    }

    // reduce over corners (xor 4, 8) and point-halves (xor 16)
    #pragma unroll
    for (int m = 4; m <= 16; m <<= 1)
        #pragma unroll
        for (int i = 0; i < 8; i++)
            acc[i] += __shfl_xor_sync(0xffffffffu, acc[i], m);

    if (lane < 4) {
        const float inv = 1.f / fmaxf((float)cnt, 1.0f);
        float4 o0 = make_float4(acc[0] * inv, acc[1] * inv, acc[2] * inv, acc[3] * inv);
        float4 o1 = make_float4(acc[4] * inv, acc[5] * inv, acc[6] * inv, acc[7] * inv);
        float* dst = g_slots + (size_t)n * CDIM + h * DHEAD + g2 * 8;
        *reinterpret_cast<float4*>(dst)     = o0;
        *reinterpret_cast<float4*>(dst + 4) = o1;
    }
}

// ---------------------------------------------------------------------------
// Kernel D: out = slots @ Wout + bout + residual(query).
// 512 threads, 32 rows (grid 200), micro-tile 1 row x 8 cols.
// ---------------------------------------------------------------------------
__global__ void __launch_bounds__(512)
k_out_t(const float* __restrict__ query,
        const float* __restrict__ Wout,
        const float* __restrict__ bout,
        float* __restrict__ out) {
    extern __shared__ float smem[];
    float* sW = smem;                 // [128][128]
    float* sA = smem + 128 * 128;     // [32][128]

    const int n0  = blockIdx.x * TMD;
    const int tid = threadIdx.x;

    for (int idx = tid; idx < 128 * 128 / 4; idx += 512)
        reinterpret_cast<float4*>(sW)[idx] = reinterpret_cast<const float4*>(Wout)[idx];
    for (int idx = tid; idx < TMD * 128 / 4; idx += 512)
        reinterpret_cast<float4*>(sA)[idx] =
            reinterpret_cast<const float4*>(g_slots + (size_t)n0 * CDIM)[idx];
    __syncthreads();

    const int tx = tid & 15;
    const int ry = tid >> 4;          // 0..31 = row

    float acc[8];
    #pragma unroll
    for (int j = 0; j < 8; j++) acc[j] = 0.f;

    for (int k4 = 0; k4 < 128; k4 += 4) {
        const float4 a0 = *reinterpret_cast<const float4*>(&sA[ry * 128 + k4]);
        #pragma unroll
        for (int kk = 0; kk < 4; kk++) {
            const float ak = (&a0.x)[kk];
            const float4 w0 = *reinterpret_cast<const float4*>(&sW[(k4 + kk) * 128 + tx * 8]);
            const float4 w1 = *reinterpret_cast<const float4*>(&sW[(k4 + kk) * 128 + tx * 8 + 4]);
            acc[0] = fmaf(ak, w0.x, acc[0]);
            acc[1] = fmaf(ak, w0.y, acc[1]);
            acc[2] = fmaf(ak, w0.z, acc[2]);
            acc[3] = fmaf(ak, w0.w, acc[3]);
            acc[4] = fmaf(ak, w1.x, acc[4]);
            acc[5] = fmaf(ak, w1.y, acc[5]);
            acc[6] = fmaf(ak, w1.z, acc[6]);
            acc[7] = fmaf(ak, w1.w, acc[7]);
        }
    }

    const float4 b0 = *reinterpret_cast<const float4*>(&bout[tx * 8]);
    const float4 b1 = *reinterpret_cast<const float4*>(&bout[tx * 8 + 4]);
    const int row = n0 + ry;
    const float4 q0 = *reinterpret_cast<const float4*>(&query[row * CDIM + tx * 8]);
    const float4 q1 = *reinterpret_cast<const float4*>(&query[row * CDIM + tx * 8 + 4]);
    float4 o0 = make_float4(acc[0] + b0.x + q0.x, acc[1] + b0.y + q0.y,
                            acc[2] + b0.z + q0.z, acc[3] + b0.w + q0.w);
    float4 o1 = make_float4(acc[4] + b1.x + q1.x, acc[5] + b1.y + q1.y,
                            acc[6] + b1.z + q1.z, acc[7] + b1.w + q1.w);
    *reinterpret_cast<float4*>(&out[row * CDIM + tx * 8])     = o0;
    *reinterpret_cast<float4*>(&out[row * CDIM + tx * 8 + 4]) = o1;
}

// ---------------------------------------------------------------------------
// Launch. Input order per setup_inputs:
// 0 query, 1 key (unused), 2 value, 3 query_pos, 4 reference_points_cam,
// 5 bev_mask, 6 spatial_shapes, 7 level_start_index, 8 Wv, 9 bv, 10 Woff,
// 11 boff, 12 Wattn, 13 battn, 14 Wout, 15 bout
// ---------------------------------------------------------------------------
extern "C" void kernel_launch(void* const* d_in, const int* in_sizes, int n_in,
                              void* d_out, int out_size) {
    const float* query = (const float*)d_in[0];
    const float* value = (const float*)d_in[2];
    const float* qpos  = (const float*)d_in[3];
    const float* refp  = (const float*)d_in[4];
    const int*   bmask = (const int*)d_in[5];
    const float* Wv    = (const float*)d_in[8];
    const float* bv    = (const float*)d_in[9];
    const float* Woff  = (const float*)d_in[10];
    const float* boff  = (const float*)d_in[11];
    const float* Wattn = (const float*)d_in[12];
    const float* battn = (const float*)d_in[13];
    const float* Wout  = (const float*)d_in[14];
    const float* bout  = (const float*)d_in[15];
    float* out = (float*)d_out;

    const int smemA = (128 * NCOMB + TMB * 128) * sizeof(float);   // 155648
    const int smemB = (128 * 128 + TMB * 128) * sizeof(float);     // 98304
    const int smemD = (128 * 128 + TMD * 128) * sizeof(float);     // 81920

    cudaFuncSetAttribute(k_proj_off_attn_t, cudaFuncAttributeMaxDynamicSharedMemorySize, smemA);
    cudaFuncSetAttribute(k_proj_val_t,      cudaFuncAttributeMaxDynamicSharedMemorySize, smemB);
    cudaFuncSetAttribute(k_out_t,           cudaFuncAttributeMaxDynamicSharedMemorySize, smemD);

    // Fork: A runs on the aux stream, B on the main stream; join before sampling.
    cudaEventRecord(g_aux.evFork, 0);
    cudaStreamWaitEvent(g_aux.s, g_aux.evFork, 0);
    k_proj_off_attn_t<<<NQ / TMB, 512, smemA, g_aux.s>>>(query, qpos, Woff, boff, Wattn, battn);
    cudaEventRecord(g_aux.evJoin, g_aux.s);

    k_proj_val_t<<<SCAM * MPIX / TMB, 512, smemB>>>(value, Wv, bv);
    cudaStreamWaitEvent(0, g_aux.evJoin, 0);

    k_sample<<<NQ, CDIM>>>(refp, bmask);
    k_out_t<<<NQ / TMD, 512, smemD>>>(query, Wout, bout, out);
}

// round 7
// speedup vs baseline: 1.3132x; 1.3132x over previous
#include <cuda_runtime.h>
#include <cuda_bf16.h>
#include <cuda_fp8.h>
#include <math.h>

// Problem constants
#define NQ      6400
#define CDIM    128
#define SCAM    6
#define MPIX    2816     // 32*88
#define HEADS   4
#define POINTS  20
#define HSZ     32
#define WSZ     88
#define DHEAD   32
#define DANCH   4
#define OFF_W   160      // HEADS*POINTS*2
#define ATTN_W  80       // HEADS*POINTS
#define NCOMB   240      // OFF_W + ATTN_W

#define TM      64       // rows per GEMM block

// Scratch (device globals -- no allocation allowed)
__device__ float         g_off[NQ * OFF_W];              // sampling offsets, already /norm
__device__ float         g_aw [NQ * ATTN_W];             // softmaxed attention weights
__device__ unsigned char g_val[SCAM * MPIX * CDIM];      // projected value, (s,pix,c) fp8 e4m3
__device__ float         g_slots[NQ * CDIM];             // per-query accumulated slots

// ---------------------------------------------------------------------------
// Kernel A (R5 shape): q = query+query_pos; [offsets | attn logits]
// 256 threads, 64 rows x 240 cols, micro-tile 4 rows x 15 cols.
// ---------------------------------------------------------------------------
__global__ void k_proj_off_attn_t(const float* __restrict__ query,
                                  const float* __restrict__ qpos,
                                  const float* __restrict__ Woff,
                                  const float* __restrict__ boff,
                                  const float* __restrict__ Wattn,
                                  const float* __restrict__ battn) {
    extern __shared__ float smem[];
    float* sW = smem;                 // [128][240]
    float* sA = smem + 128 * NCOMB;   // [64][128]

    const int n0  = blockIdx.x * TM;
    const int tid = threadIdx.x;

    for (int idx = tid; idx < 128 * NCOMB; idx += 256) {
        const int k = idx / NCOMB, n = idx - k * NCOMB;
        sW[idx] = (n < OFF_W) ? Woff[k * OFF_W + n] : Wattn[k * ATTN_W + (n - OFF_W)];
    }
    for (int idx = tid; idx < TM * 128; idx += 256) {
        const int g = n0 * CDIM + idx;
        sA[idx] = query[g] + qpos[g];
    }
    __syncthreads();

    const int ty = tid >> 4;   // rows ty*4..ty*4+3
    const int tx = tid & 15;   // cols tx + 16*j

    float acc[4][15];
    #pragma unroll
    for (int i = 0; i < 4; i++)
        #pragma unroll
        for (int j = 0; j < 15; j++) acc[i][j] = 0.f;

    #pragma unroll 4
    for (int k = 0; k < 128; k++) {
        float a[4];
        #pragma unroll
        for (int i = 0; i < 4; i++) a[i] = sA[(ty * 4 + i) * 128 + k];
        #pragma unroll
        for (int j = 0; j < 15; j++) {
            const float w = sW[k * NCOMB + tx + 16 * j];
            #pragma unroll
            for (int i = 0; i < 4; i++) acc[i][j] = fmaf(a[i], w, acc[i][j]);
        }
    }
    __syncthreads();

    #pragma unroll
    for (int i = 0; i < 4; i++)
        #pragma unroll
        for (int j = 0; j < 15; j++)
            sW[(ty * 4 + i) * NCOMB + tx + 16 * j] = acc[i][j];
    __syncthreads();

    for (int idx = tid; idx < TM * OFF_W; idx += 256) {
        const int r = idx / OFF_W, t = idx - r * OFF_W;
        const float v = sW[r * NCOMB + t] + boff[t];
        g_off[(n0 + r) * OFF_W + t] = v * ((t & 1) ? (1.f / 32.f) : (1.f / 88.f));
    }
    {
        const int r = tid >> 2, h = tid & 3;
        float lg[POINTS];
        float mx = -1e30f;
        #pragma unroll
        for (int p = 0; p < POINTS; p++) {
            lg[p] = sW[r * NCOMB + OFF_W + h * POINTS + p] + battn[h * POINTS + p];
            mx = fmaxf(mx, lg[p]);
        }
        float sum = 0.f;
        #pragma unroll
        for (int p = 0; p < POINTS; p++) { lg[p] = __expf(lg[p] - mx); sum += lg[p]; }
        const float inv = 1.f / sum;
        #pragma unroll
        for (int p = 0; p < POINTS; p++)
            g_aw[(n0 + r) * ATTN_W + h * POINTS + p] = lg[p] * inv;
    }
}

// ---------------------------------------------------------------------------
// Kernel B (R5 shape): val = value @ Wv + bv -> fp8 e4m3, layout (s,pix,c).
// 256 threads, micro-tile 4x8, vector weight LDS, packed uint2 fp8 stores.
// ---------------------------------------------------------------------------
__global__ void k_proj_val_t(const float* __restrict__ value,
                             const float* __restrict__ Wv,
                             const float* __restrict__ bv) {
    extern __shared__ float smem[];
    float* sW = smem;                 // [128][128]
    float* sA = smem + 128 * 128;     // [64][128]

    const int n0  = blockIdx.x * TM;
    const int tid = threadIdx.x;

    for (int idx = tid; idx < 128 * 128 / 4; idx += 256)
        reinterpret_cast<float4*>(sW)[idx] = reinterpret_cast<const float4*>(Wv)[idx];
    for (int idx = tid; idx < TM * 128 / 4; idx += 256)
        reinterpret_cast<float4*>(sA)[idx] =
            reinterpret_cast<const float4*>(value + (size_t)n0 * CDIM)[idx];
    __syncthreads();

    const int ty = tid >> 4;
    const int tx = tid & 15;

    float acc[4][8];
    #pragma unroll
    for (int i = 0; i < 4; i++)
        #pragma unroll
        for (int j = 0; j < 8; j++) acc[i][j] = 0.f;

    #pragma unroll 4
    for (int k = 0; k < 128; k++) {
        float a[4];
        #pragma unroll
        for (int i = 0; i < 4; i++) a[i] = sA[(ty * 4 + i) * 128 + k];
        const float4 w0 = *reinterpret_cast<const float4*>(&sW[k * 128 + tx * 8]);
        const float4 w1 = *reinterpret_cast<const float4*>(&sW[k * 128 + tx * 8 + 4]);
        #pragma unroll
        for (int i = 0; i < 4; i++) {
            acc[i][0] = fmaf(a[i], w0.x, acc[i][0]);
            acc[i][1] = fmaf(a[i], w0.y, acc[i][1]);
            acc[i][2] = fmaf(a[i], w0.z, acc[i][2]);
            acc[i][3] = fmaf(a[i], w0.w, acc[i][3]);
            acc[i][4] = fmaf(a[i], w1.x, acc[i][4]);
            acc[i][5] = fmaf(a[i], w1.y, acc[i][5]);
            acc[i][6] = fmaf(a[i], w1.z, acc[i][6]);
            acc[i][7] = fmaf(a[i], w1.w, acc[i][7]);
        }
    }

    const float4 b0 = *reinterpret_cast<const float4*>(&bv[tx * 8]);
    const float4 b1 = *reinterpret_cast<const float4*>(&bv[tx * 8 + 4]);
    #pragma unroll
    for (int i = 0; i < 4; i++) {
        const int row = n0 + ty * 4 + i;
        const __nv_fp8x2_storage_t p0 = __nv_cvt_float2_to_fp8x2(
            make_float2(acc[i][0] + b0.x, acc[i][1] + b0.y), __NV_SATFINITE, __NV_E4M3);
        const __nv_fp8x2_storage_t p1 = __nv_cvt_float2_to_fp8x2(
            make_float2(acc[i][2] + b0.z, acc[i][3] + b0.w), __NV_SATFINITE, __NV_E4M3);
        const __nv_fp8x2_storage_t p2 = __nv_cvt_float2_to_fp8x2(
            make_float2(acc[i][4] + b1.x, acc[i][5] + b1.y), __NV_SATFINITE, __NV_E4M3);
        const __nv_fp8x2_storage_t p3 = __nv_cvt_float2_to_fp8x2(
            make_float2(acc[i][6] + b1.z, acc[i][7] + b1.w), __NV_SATFINITE, __NV_E4M3);
        uint2 u;
        u.x = (unsigned)p0 | ((unsigned)p1 << 16);
        u.y = (unsigned)p2 | ((unsigned)p3 << 16);
        *reinterpret_cast<uint2*>(&g_val[(size_t)row * CDIM + tx * 8]) = u;
    }
}

// ---------------------------------------------------------------------------
// Kernel C: bilinear sampling on the fp8 value cache.
// Block = query (128 threads), warp = head.
// lane = (half<<4) | (corner<<2) | chgrp; 2 points x 4 corners x 32 channels
// per warp iteration, one LDG.64 (8 fp8) per lane. Offsets/attn-weights
// hoisted into registers. Butterfly reduction (xor 4, 8, 16) at the end.
// ---------------------------------------------------------------------------
__device__ __forceinline__ float2 fp8x2_to_float2(unsigned short v) {
    const __half2_raw hr = __nv_cvt_fp8x2_to_halfraw2((__nv_fp8x2_storage_t)v, __NV_E4M3);
    return __half22float2(*reinterpret_cast<const __half2*>(&hr));
}

__global__ void k_sample(const float* __restrict__ refpts,   // (S,1,N,4,2)
                         const int* __restrict__ bmask) {    // (S,1,N,4) 4-byte flags
    const int n    = blockIdx.x;
    const int t    = threadIdx.x;
    const int h    = t >> 5;
    const int lane = t & 31;
    const int half = lane >> 4;        // which point of the pair
    const int c2   = (lane >> 2) & 3;  // bilinear corner
    const int dx   = c2 & 1, dy = c2 >> 1;
    const int g2   = lane & 3;         // channel group of 8

    __shared__ float sOff[OFF_W];
    __shared__ float sAw[ATTN_W];
    __shared__ float sRef[SCAM * 8];
    __shared__ int   sAct[SCAM];
    __shared__ int   sCnt;

    for (int i = t; i < OFF_W; i += 128)  sOff[i] = g_off[n * OFF_W + i];
    for (int i = t; i < ATTN_W; i += 128) sAw[i]  = g_aw[n * ATTN_W + i];
    for (int i = t; i < SCAM * 8; i += 128) {
        const int s = i >> 3, e = i & 7;
        sRef[i] = refpts[((size_t)s * NQ + n) * 8 + e];
    }
    if (t == 0) {
        int cnt = 0;
        #pragma unroll
        for (int s = 0; s < SCAM; s++) {
            const int4 mw = *reinterpret_cast<const int4*>(bmask + ((size_t)s * NQ + n) * DANCH);
            if (mw.x | mw.y | mw.z | mw.w) sAct[cnt++] = s;
        }
        sCnt = cnt;
    }
    __syncthreads();

    // hoist this lane's 10 points: offsets and attention weights
    float ox[10], oy[10], wp[10];
    #pragma unroll
    for (int i = 0; i < 10; i++) {
        const int p = 2 * i + half;
        ox[i] = sOff[h * 40 + p * 2 + 0];
        oy[i] = sOff[h * 40 + p * 2 + 1];
        wp[i] = sAw[h * POINTS + p];
    }

    float acc[8];
    #pragma unroll
    for (int i = 0; i < 8; i++) acc[i] = 0.f;

    const int cnt = sCnt;
    for (int j = 0; j < cnt; j++) {
        const int s = sAct[j];
        const unsigned char* __restrict__ imgb =
            g_val + (size_t)s * MPIX * CDIM + h * DHEAD + g2 * 8;
        const float* __restrict__ rf = &sRef[s * 8];
        // anchor d = half for even i, 2+half for odd i
        const float fx0 = rf[half * 2 + 0], fy0 = rf[half * 2 + 1];
        const float fx2 = rf[half * 2 + 4], fy2 = rf[half * 2 + 5];

        #pragma unroll
        for (int i = 0; i < 10; i++) {
            const float bx = (i & 1) ? fx2 : fx0;
            const float by = (i & 1) ? fy2 : fy0;
            const float x = (bx + ox[i]) * 88.f - 0.5f;
            const float y = (by + oy[i]) * 32.f - 0.5f;
            const float x0f = floorf(x), y0f = floorf(y);
            const float wx = x - x0f, wy = y - y0f;
            const int xx = (int)x0f + dx;
            const int yy = (int)y0f + dy;
            const float wc = (dx ? wx : 1.f - wx) * (dy ? wy : 1.f - wy) * wp[i];

            if ((unsigned)xx < (unsigned)WSZ && (unsigned)yy < (unsigned)HSZ) {
                const uint2 raw = *reinterpret_cast<const uint2*>(imgb + (yy * WSZ + xx) * CDIM);
                const float2 f0 = fp8x2_to_float2((unsigned short)(raw.x & 0xffffu));
                const float2 f1 = fp8x2_to_float2((unsigned short)(raw.x >> 16));
                const float2 f2 = fp8x2_to_float2((unsigned short)(raw.y & 0xffffu));
                const float2 f3 = fp8x2_to_float2((unsigned short)(raw.y >> 16));
                acc[0] = fmaf(wc, f0.x, acc[0]);
                acc[1] = fmaf(wc, f0.y, acc[1]);
                acc[2] = fmaf(wc, f1.x, acc[2]);
                acc[3] = fmaf(wc, f1.y, acc[3]);
                acc[4] = fmaf(wc, f2.x, acc[4]);
                acc[5] = fmaf(wc, f2.y, acc[5]);
                acc[6] = fmaf(wc, f3.x, acc[6]);
                acc[7] = fmaf(wc, f3.y, acc[7]);
            }
        }
    }

    // reduce over corners (xor 4, 8) and point-halves (xor 16)
    #pragma unroll
    for (int m = 4; m <= 16; m <<= 1)
        #pragma unroll
        for (int i = 0; i < 8; i++)
            acc[i] += __shfl_xor_sync(0xffffffffu, acc[i], m);

    if (lane < 4) {
        const float inv = 1.f / fmaxf((float)cnt, 1.0f);
        float4 o0 = make_float4(acc[0] * inv, acc[1] * inv, acc[2] * inv, acc[3] * inv);
        float4 o1 = make_float4(acc[4] * inv, acc[5] * inv, acc[6] * inv, acc[7] * inv);
        float* dst = g_slots + (size_t)n * CDIM + h * DHEAD + g2 * 8;
        *reinterpret_cast<float4*>(dst)     = o0;
        *reinterpret_cast<float4*>(dst + 4) = o1;
    }
}

// ---------------------------------------------------------------------------
// Kernel D (R5 shape): out = slots @ Wout + bout + residual(query).
// 256 threads, micro-tile 4x8.
// ---------------------------------------------------------------------------
__global__ void k_out_t(const float* __restrict__ query,
                        const float* __restrict__ Wout,
                        const float* __restrict__ bout,
                        float* __restrict__ out) {
    extern __shared__ float smem[];
    float* sW = smem;                 // [128][128]
    float* sA = smem + 128 * 128;     // [64][128]

    const int n0  = blockIdx.x * TM;
    const int tid = threadIdx.x;

    for (int idx = tid; idx < 128 * 128 / 4; idx += 256)
        reinterpret_cast<float4*>(sW)[idx] = reinterpret_cast<const float4*>(Wout)[idx];
    for (int idx = tid; idx < TM * 128 / 4; idx += 256)
        reinterpret_cast<float4*>(sA)[idx] =
            reinterpret_cast<const float4*>(g_slots + (size_t)n0 * CDIM)[idx];
    __syncthreads();

    const int ty = tid >> 4;
    const int tx = tid & 15;

    float acc[4][8];
    #pragma unroll
    for (int i = 0; i < 4; i++)
        #pragma unroll
        for (int j = 0; j < 8; j++) acc[i][j] = 0.f;

    #pragma unroll 4
    for (int k = 0; k < 128; k++) {
        float a[4];
        #pragma unroll
        for (int i = 0; i < 4; i++) a[i] = sA[(ty * 4 + i) * 128 + k];
        const float4 w0 = *reinterpret_cast<const float4*>(&sW[k * 128 + tx * 8]);
        const float4 w1 = *reinterpret_cast<const float4*>(&sW[k * 128 + tx * 8 + 4]);
        #pragma unroll
        for (int i = 0; i < 4; i++) {
            acc[i][0] = fmaf(a[i], w0.x, acc[i][0]);
            acc[i][1] = fmaf(a[i], w0.y, acc[i][1]);
            acc[i][2] = fmaf(a[i], w0.z, acc[i][2]);
            acc[i][3] = fmaf(a[i], w0.w, acc[i][3]);
            acc[i][4] = fmaf(a[i], w1.x, acc[i][4]);
            acc[i][5] = fmaf(a[i], w1.y, acc[i][5]);
            acc[i][6] = fmaf(a[i], w1.z, acc[i][6]);
            acc[i][7] = fmaf(a[i], w1.w, acc[i][7]);
        }
    }

    const float4 b0 = *reinterpret_cast<const float4*>(&bout[tx * 8]);
    const float4 b1 = *reinterpret_cast<const float4*>(&bout[tx * 8 + 4]);
    #pragma unroll
    for (int i = 0; i < 4; i++) {
        const int row = n0 + ty * 4 + i;
        const float4 q0 = *reinterpret_cast<const float4*>(&query[row * CDIM + tx * 8]);
        const float4 q1 = *reinterpret_cast<const float4*>(&query[row * CDIM + tx * 8 + 4]);
        float4 o0 = make_float4(acc[i][0] + b0.x + q0.x, acc[i][1] + b0.y + q0.y,
                                acc[i][2] + b0.z + q0.z, acc[i][3] + b0.w + q0.w);
        float4 o1 = make_float4(acc[i][4] + b1.x + q1.x, acc[i][5] + b1.y + q1.y,
                                acc[i][6] + b1.z + q1.z, acc[i][7] + b1.w + q1.w);
        *reinterpret_cast<float4*>(&out[row * CDIM + tx * 8])     = o0;
        *reinterpret_cast<float4*>(&out[row * CDIM + tx * 8 + 4]) = o1;
    }
}

// ---------------------------------------------------------------------------
// Launch. Input order per setup_inputs:
// 0 query, 1 key (unused), 2 value, 3 query_pos, 4 reference_points_cam,
// 5 bev_mask, 6 spatial_shapes, 7 level_start_index, 8 Wv, 9 bv, 10 Woff,
// 11 boff, 12 Wattn, 13 battn, 14 Wout, 15 bout
// ---------------------------------------------------------------------------
extern "C" void kernel_launch(void* const* d_in, const int* in_sizes, int n_in,
                              void* d_out, int out_size) {
    const float* query = (const float*)d_in[0];
    const float* value = (const float*)d_in[2];
    const float* qpos  = (const float*)d_in[3];
    const float* refp  = (const float*)d_in[4];
    const int*   bmask = (const int*)d_in[5];
    const float* Wv    = (const float*)d_in[8];
    const float* bv    = (const float*)d_in[9];
    const float* Woff  = (const float*)d_in[10];
    const float* boff  = (const float*)d_in[11];
    const float* Wattn = (const float*)d_in[12];
    const float* battn = (const float*)d_in[13];
    const float* Wout  = (const float*)d_in[14];
    const float* bout  = (const float*)d_in[15];
    float* out = (float*)d_out;

    const int smemA  = (128 * NCOMB + TM * 128) * sizeof(float);   // 155648
    const int smemWv = (128 * 128 + TM * 128) * sizeof(float);     // 98304

    cudaFuncSetAttribute(k_proj_off_attn_t, cudaFuncAttributeMaxDynamicSharedMemorySize, smemA);
    cudaFuncSetAttribute(k_proj_val_t,      cudaFuncAttributeMaxDynamicSharedMemorySize, smemWv);
    cudaFuncSetAttribute(k_out_t,           cudaFuncAttributeMaxDynamicSharedMemorySize, smemWv);

    k_proj_off_attn_t<<<NQ / TM, 256, smemA>>>(query, qpos, Woff, boff, Wattn, battn);
    k_proj_val_t<<<SCAM * MPIX / TM, 256, smemWv>>>(value, Wv, bv);
    k_sample<<<NQ, CDIM>>>(refp, bmask);
    k_out_t<<<NQ / TM, 256, smemWv>>>(query, Wout, bout, out);
}

// round 8
// speedup vs baseline: 1.6239x; 1.2366x over previous
#include <cuda_runtime.h>
#include <cuda_bf16.h>
#include <cuda_fp8.h>
#include <math.h>

// Problem constants
#define NQ      6400
#define CDIM    128
#define SCAM    6
#define MPIX    2816     // 32*88
#define HEADS   4
#define POINTS  20
#define HSZ     32
#define WSZ     88
#define DHEAD   32
#define DANCH   4
#define OFF_W   160      // HEADS*POINTS*2
#define ATTN_W  80       // HEADS*POINTS
#define NCOMB   240      // OFF_W + ATTN_W

#define TM      64       // rows per GEMM block

// Scratch (device globals -- no allocation allowed)
__device__ float         g_off[NQ * OFF_W];              // sampling offsets, already /norm
__device__ float         g_aw [NQ * ATTN_W];             // softmaxed attention weights
__device__ unsigned char g_val[SCAM * MPIX * CDIM];      // projected value, (s,pix,c) fp8 e4m3
__device__ float         g_slots[NQ * CDIM];             // per-query accumulated slots

// ---------------------------------------------------------------------------
// Kernel A (unchanged R7 shape): q = query+query_pos; [offsets | attn logits]
// ---------------------------------------------------------------------------
__global__ void k_proj_off_attn_t(const float* __restrict__ query,
                                  const float* __restrict__ qpos,
                                  const float* __restrict__ Woff,
                                  const float* __restrict__ boff,
                                  const float* __restrict__ Wattn,
                                  const float* __restrict__ battn) {
    extern __shared__ float smem[];
    float* sW = smem;                 // [128][240]
    float* sA = smem + 128 * NCOMB;   // [64][128]

    const int n0  = blockIdx.x * TM;
    const int tid = threadIdx.x;

    for (int idx = tid; idx < 128 * NCOMB; idx += 256) {
        const int k = idx / NCOMB, n = idx - k * NCOMB;
        sW[idx] = (n < OFF_W) ? Woff[k * OFF_W + n] : Wattn[k * ATTN_W + (n - OFF_W)];
    }
    for (int idx = tid; idx < TM * 128; idx += 256) {
        const int g = n0 * CDIM + idx;
        sA[idx] = query[g] + qpos[g];
    }
    __syncthreads();

    const int ty = tid >> 4;   // rows ty*4..ty*4+3
    const int tx = tid & 15;   // cols tx + 16*j

    float acc[4][15];
    #pragma unroll
    for (int i = 0; i < 4; i++)
        #pragma unroll
        for (int j = 0; j < 15; j++) acc[i][j] = 0.f;

    #pragma unroll 4
    for (int k = 0; k < 128; k++) {
        float a[4];
        #pragma unroll
        for (int i = 0; i < 4; i++) a[i] = sA[(ty * 4 + i) * 128 + k];
        #pragma unroll
        for (int j = 0; j < 15; j++) {
            const float w = sW[k * NCOMB + tx + 16 * j];
            #pragma unroll
            for (int i = 0; i < 4; i++) acc[i][j] = fmaf(a[i], w, acc[i][j]);
        }
    }
    __syncthreads();

    #pragma unroll
    for (int i = 0; i < 4; i++)
        #pragma unroll
        for (int j = 0; j < 15; j++)
            sW[(ty * 4 + i) * NCOMB + tx + 16 * j] = acc[i][j];
    __syncthreads();

    for (int idx = tid; idx < TM * OFF_W; idx += 256) {
        const int r = idx / OFF_W, t = idx - r * OFF_W;
        const float v = sW[r * NCOMB + t] + boff[t];
        g_off[(n0 + r) * OFF_W + t] = v * ((t & 1) ? (1.f / 32.f) : (1.f / 88.f));
    }
    {
        const int r = tid >> 2, h = tid & 3;
        float lg[POINTS];
        float mx = -1e30f;
        #pragma unroll
        for (int p = 0; p < POINTS; p++) {
            lg[p] = sW[r * NCOMB + OFF_W + h * POINTS + p] + battn[h * POINTS + p];
            mx = fmaxf(mx, lg[p]);
        }
        float sum = 0.f;
        #pragma unroll
        for (int p = 0; p < POINTS; p++) { lg[p] = __expf(lg[p] - mx); sum += lg[p]; }
        const float inv = 1.f / sum;
        #pragma unroll
        for (int p = 0; p < POINTS; p++)
            g_aw[(n0 + r) * ATTN_W + h * POINTS + p] = lg[p] * inv;
    }
}

// ---------------------------------------------------------------------------
// Kernel B (col-split): val = value @ Wv + bv -> fp8 e4m3, layout (s,pix,c).
// Block = (row tile 64) x (col half 64). 256 threads, micro-tile 4x4.
// smem 64KB -> up to 3 CTAs/SM. grid = 528.
// ---------------------------------------------------------------------------
__global__ void k_proj_val_t(const float* __restrict__ value,
                             const float* __restrict__ Wv,
                             const float* __restrict__ bv) {
    extern __shared__ float smem[];
    float* sW = smem;                 // [128][64]
    float* sA = smem + 128 * 64;      // [64][128]

    const int bx  = blockIdx.x;
    const int r0  = (bx >> 1) * TM;   // row tile base
    const int ch  = (bx & 1) * 64;    // column half base
    const int tid = threadIdx.x;

    for (int idx = tid; idx < 128 * 16; idx += 256) {           // 2048 float4
        const int k = idx >> 4, c4 = idx & 15;
        reinterpret_cast<float4*>(sW)[idx] =
            *reinterpret_cast<const float4*>(&Wv[k * 128 + ch + c4 * 4]);
    }
    for (int idx = tid; idx < TM * 128 / 4; idx += 256)
        reinterpret_cast<float4*>(sA)[idx] =
            reinterpret_cast<const float4*>(value + (size_t)r0 * CDIM)[idx];
    __syncthreads();

    const int ty = tid >> 4;   // rows ty*4..ty*4+3
    const int tx = tid & 15;   // cols tx*4..tx*4+3 (within half)

    float acc[4][4];
    #pragma unroll
    for (int i = 0; i < 4; i++)
        #pragma unroll
        for (int j = 0; j < 4; j++) acc[i][j] = 0.f;

    #pragma unroll 4
    for (int k = 0; k < 128; k++) {
        float a[4];
        #pragma unroll
        for (int i = 0; i < 4; i++) a[i] = sA[(ty * 4 + i) * 128 + k];
        const float4 w = *reinterpret_cast<const float4*>(&sW[k * 64 + tx * 4]);
        #pragma unroll
        for (int i = 0; i < 4; i++) {
            acc[i][0] = fmaf(a[i], w.x, acc[i][0]);
            acc[i][1] = fmaf(a[i], w.y, acc[i][1]);
            acc[i][2] = fmaf(a[i], w.z, acc[i][2]);
            acc[i][3] = fmaf(a[i], w.w, acc[i][3]);
        }
    }

    const float4 b = *reinterpret_cast<const float4*>(&bv[ch + tx * 4]);
    #pragma unroll
    for (int i = 0; i < 4; i++) {
        const int row = r0 + ty * 4 + i;
        const __nv_fp8x2_storage_t p0 = __nv_cvt_float2_to_fp8x2(
            make_float2(acc[i][0] + b.x, acc[i][1] + b.y), __NV_SATFINITE, __NV_E4M3);
        const __nv_fp8x2_storage_t p1 = __nv_cvt_float2_to_fp8x2(
            make_float2(acc[i][2] + b.z, acc[i][3] + b.w), __NV_SATFINITE, __NV_E4M3);
        const unsigned u = (unsigned)p0 | ((unsigned)p1 << 16);
        *reinterpret_cast<unsigned*>(&g_val[(size_t)row * CDIM + ch + tx * 4]) = u;
    }
}

// ---------------------------------------------------------------------------
// Kernel C: bilinear sampling on the fp8 value cache.
// Block = query (128 threads), warp = head.
// lane = (pt<<3) | (corner<<1) | chgrp: 4 points x 4 corners x 2 channel
// groups of 16 per warp iteration; each lane does one LDG.128 (16 fp8).
// Anchor d = p&3 = pt is a per-lane constant. Butterfly reduce xor 2,4,8,16.
// ---------------------------------------------------------------------------
__device__ __forceinline__ float2 fp8x2_to_float2(unsigned short v) {
    const __half2_raw hr = __nv_cvt_fp8x2_to_halfraw2((__nv_fp8x2_storage_t)v, __NV_E4M3);
    return __half22float2(*reinterpret_cast<const __half2*>(&hr));
}

__global__ void k_sample(const float* __restrict__ refpts,   // (S,1,N,4,2)
                         const int* __restrict__ bmask) {    // (S,1,N,4) 4-byte flags
    const int n      = blockIdx.x;
    const int t      = threadIdx.x;
    const int h      = t >> 5;
    const int lane   = t & 31;
    const int chgrp  = lane & 1;         // 16-channel group
    const int corner = (lane >> 1) & 3;  // bilinear corner
    const int dx     = corner & 1, dy = corner >> 1;
    const int pt     = (lane >> 3) & 3;  // point slot; p = 4*i + pt, anchor d = pt

    __shared__ float sOff[OFF_W];
    __shared__ float sAw[ATTN_W];
    __shared__ float sRef[SCAM * 8];
    __shared__ int   sAct[SCAM];
    __shared__ int   sCnt;

    for (int i = t; i < OFF_W; i += 128)  sOff[i] = g_off[n * OFF_W + i];
    for (int i = t; i < ATTN_W; i += 128) sAw[i]  = g_aw[n * ATTN_W + i];
    for (int i = t; i < SCAM * 8; i += 128) {
        const int s = i >> 3, e = i & 7;
        sRef[i] = refpts[((size_t)s * NQ + n) * 8 + e];
    }
    if (t == 0) {
        int cnt = 0;
        #pragma unroll
        for (int s = 0; s < SCAM; s++) {
            const int4 mw = *reinterpret_cast<const int4*>(bmask + ((size_t)s * NQ + n) * DANCH);
            if (mw.x | mw.y | mw.z | mw.w) sAct[cnt++] = s;
        }
        sCnt = cnt;
    }
    __syncthreads();

    // hoist this lane's 5 points (p = 4i + pt): offsets and attention weights
    float ox[5], oy[5], wp[5];
    #pragma unroll
    for (int i = 0; i < 5; i++) {
        const int p = 4 * i + pt;
        ox[i] = sOff[h * 40 + p * 2 + 0];
        oy[i] = sOff[h * 40 + p * 2 + 1];
        wp[i] = sAw[h * POINTS + p];
    }

    float acc[16];
    #pragma unroll
    for (int i = 0; i < 16; i++) acc[i] = 0.f;

    const int cnt = sCnt;
    for (int j = 0; j < cnt; j++) {
        const int s = sAct[j];
        const unsigned char* __restrict__ imgb =
            g_val + (size_t)s * MPIX * CDIM + h * DHEAD + chgrp * 16;
        const float fx = sRef[s * 8 + pt * 2 + 0];
        const float fy = sRef[s * 8 + pt * 2 + 1];

        #pragma unroll
        for (int i = 0; i < 5; i++) {
            const float x = (fx + ox[i]) * 88.f - 0.5f;
            const float y = (fy + oy[i]) * 32.f - 0.5f;
            const float x0f = floorf(x), y0f = floorf(y);
            const float wx = x - x0f, wy = y - y0f;
            const int xx = (int)x0f + dx;
            const int yy = (int)y0f + dy;
            const float wc = (dx ? wx : 1.f - wx) * (dy ? wy : 1.f - wy) * wp[i];

            if ((unsigned)xx < (unsigned)WSZ && (unsigned)yy < (unsigned)HSZ) {
                const uint4 raw = *reinterpret_cast<const uint4*>(imgb + (yy * WSZ + xx) * CDIM);
                const unsigned rw[4] = {raw.x, raw.y, raw.z, raw.w};
                #pragma unroll
                for (int q = 0; q < 4; q++) {
                    const float2 lo = fp8x2_to_float2((unsigned short)(rw[q] & 0xffffu));
                    const float2 hi = fp8x2_to_float2((unsigned short)(rw[q] >> 16));
                    acc[q * 4 + 0] = fmaf(wc, lo.x, acc[q * 4 + 0]);
                    acc[q * 4 + 1] = fmaf(wc, lo.y, acc[q * 4 + 1]);
                    acc[q * 4 + 2] = fmaf(wc, hi.x, acc[q * 4 + 2]);
                    acc[q * 4 + 3] = fmaf(wc, hi.y, acc[q * 4 + 3]);
                }
            }
        }
    }

    // reduce over corners (xor 2, 4) and point slots (xor 8, 16)
    #pragma unroll
    for (int m = 2; m <= 16; m <<= 1)
        #pragma unroll
        for (int i = 0; i < 16; i++)
            acc[i] += __shfl_xor_sync(0xffffffffu, acc[i], m);

    if (lane < 2) {
        const float inv = 1.f / fmaxf((float)cnt, 1.0f);
        float* dst = g_slots + (size_t)n * CDIM + h * DHEAD + chgrp * 16;
        #pragma unroll
        for (int q = 0; q < 4; q++) {
            float4 o = make_float4(acc[q * 4 + 0] * inv, acc[q * 4 + 1] * inv,
                                   acc[q * 4 + 2] * inv, acc[q * 4 + 3] * inv);
            *reinterpret_cast<float4*>(dst + q * 4) = o;
        }
    }
}

// ---------------------------------------------------------------------------
// Kernel D (col-split): out = slots @ Wout + bout + residual(query).
// Block = (row tile 64) x (col half 64). 256 threads, micro-tile 4x4. grid 200.
// ---------------------------------------------------------------------------
__global__ void k_out_t(const float* __restrict__ query,
                        const float* __restrict__ Wout,
                        const float* __restrict__ bout,
                        float* __restrict__ out) {
    extern __shared__ float smem[];
    float* sW = smem;                 // [128][64]
    float* sA = smem + 128 * 64;      // [64][128]

    const int bx  = blockIdx.x;
    const int r0  = (bx >> 1) * TM;
    const int ch  = (bx & 1) * 64;
    const int tid = threadIdx.x;

    for (int idx = tid; idx < 128 * 16; idx += 256) {
        const int k = idx >> 4, c4 = idx & 15;
        reinterpret_cast<float4*>(sW)[idx] =
            *reinterpret_cast<const float4*>(&Wout[k * 128 + ch + c4 * 4]);
    }
    for (int idx = tid; idx < TM * 128 / 4; idx += 256)
        reinterpret_cast<float4*>(sA)[idx] =
            reinterpret_cast<const float4*>(g_slots + (size_t)r0 * CDIM)[idx];
    __syncthreads();

    const int ty = tid >> 4;
    const int tx = tid & 15;

    float acc[4][4];
    #pragma unroll
    for (int i = 0; i < 4; i++)
        #pragma unroll
        for (int j = 0; j < 4; j++) acc[i][j] = 0.f;

    #pragma unroll 4
    for (int k = 0; k < 128; k++) {
        float a[4];
        #pragma unroll
        for (int i = 0; i < 4; i++) a[i] = sA[(ty * 4 + i) * 128 + k];
        const float4 w = *reinterpret_cast<const float4*>(&sW[k * 64 + tx * 4]);
        #pragma unroll
        for (int i = 0; i < 4; i++) {
            acc[i][0] = fmaf(a[i], w.x, acc[i][0]);
            acc[i][1] = fmaf(a[i], w.y, acc[i][1]);
            acc[i][2] = fmaf(a[i], w.z, acc[i][2]);
            acc[i][3] = fmaf(a[i], w.w, acc[i][3]);
        }
    }

    const float4 b = *reinterpret_cast<const float4*>(&bout[ch + tx * 4]);
    #pragma unroll
    for (int i = 0; i < 4; i++) {
        const int row = r0 + ty * 4 + i;
        const float4 q = *reinterpret_cast<const float4*>(&query[row * CDIM + ch + tx * 4]);
        float4 o = make_float4(acc[i][0] + b.x + q.x, acc[i][1] + b.y + q.y,
                               acc[i][2] + b.z + q.z, acc[i][3] + b.w + q.w);
        *reinterpret_cast<float4*>(&out[row * CDIM + ch + tx * 4]) = o;
    }
}

// ---------------------------------------------------------------------------
// Launch. Input order per setup_inputs:
// 0 query, 1 key (unused), 2 value, 3 query_pos, 4 reference_points_cam,
// 5 bev_mask, 6 spatial_shapes, 7 level_start_index, 8 Wv, 9 bv, 10 Woff,
// 11 boff, 12 Wattn, 13 battn, 14 Wout, 15 bout
// ---------------------------------------------------------------------------
extern "C" void kernel_launch(void* const* d_in, const int* in_sizes, int n_in,
                              void* d_out, int out_size) {
    const float* query = (const float*)d_in[0];
    const float* value = (const float*)d_in[2];
    const float* qpos  = (const float*)d_in[3];
    const float* refp  = (const float*)d_in[4];
    const int*   bmask = (const int*)d_in[5];
    const float* Wv    = (const float*)d_in[8];
    const float* bv    = (const float*)d_in[9];
    const float* Woff  = (const float*)d_in[10];
    const float* boff  = (const float*)d_in[11];
    const float* Wattn = (const float*)d_in[12];
    const float* battn = (const float*)d_in[13];
    const float* Wout  = (const float*)d_in[14];
    const float* bout  = (const float*)d_in[15];
    float* out = (float*)d_out;

    const int smemA = (128 * NCOMB + TM * 128) * sizeof(float);   // 155648
    const int smemH = (128 * 64 + TM * 128) * sizeof(float);      // 65536

    cudaFuncSetAttribute(k_proj_off_attn_t, cudaFuncAttributeMaxDynamicSharedMemorySize, smemA);
    cudaFuncSetAttribute(k_proj_val_t,      cudaFuncAttributeMaxDynamicSharedMemorySize, smemH);
    cudaFuncSetAttribute(k_out_t,           cudaFuncAttributeMaxDynamicSharedMemorySize, smemH);

    k_proj_off_attn_t<<<NQ / TM, 256, smemA>>>(query, qpos, Woff, boff, Wattn, battn);
    k_proj_val_t<<<(SCAM * MPIX / TM) * 2, 256, smemH>>>(value, Wv, bv);
    k_sample<<<NQ, CDIM>>>(refp, bmask);
    k_out_t<<<(NQ / TM) * 2, 256, smemH>>>(query, Wout, bout, out);
}

// round 9
// speedup vs baseline: 1.7260x; 1.0629x over previous
#include <cuda_runtime.h>
#include <cuda_bf16.h>
#include <cuda_fp8.h>
#include <cuda_fp16.h>
#include <math.h>

// Problem constants
#define NQ      6400
#define CDIM    128
#define SCAM    6
#define MPIX    2816     // 32*88
#define HEADS   4
#define POINTS  20
#define HSZ     32
#define WSZ     88
#define DHEAD   32
#define DANCH   4
#define OFF_W   160      // HEADS*POINTS*2
#define ATTN_W  80       // HEADS*POINTS
#define NCOMB   240      // OFF_W + ATTN_W

#define TM      64       // rows per GEMM block

// Scratch (device globals -- no allocation allowed)
__device__ float         g_off[NQ * OFF_W];              // sampling offsets, already /norm
__device__ float         g_aw [NQ * ATTN_W];             // softmaxed attention weights
__device__ unsigned char g_val[SCAM * MPIX * CDIM];      // projected value, (s,pix,c) fp8 e4m3
__device__ float         g_slots[NQ * CDIM];             // per-query accumulated slots

// Aux stream for A||B overlap -- created once in a static initializer.
namespace {
struct AuxStream {
    cudaStream_t s;
    cudaEvent_t evFork, evJoin;
    AuxStream() {
        cudaStreamCreateWithFlags(&s, cudaStreamNonBlocking);
        cudaEventCreateWithFlags(&evFork, cudaEventDisableTiming);
        cudaEventCreateWithFlags(&evJoin, cudaEventDisableTiming);
    }
};
AuxStream g_aux;
}

// ---------------------------------------------------------------------------
// Kernel A (unchanged R8): q = query+query_pos; [offsets | attn logits]
// ---------------------------------------------------------------------------
__global__ void k_proj_off_attn_t(const float* __restrict__ query,
                                  const float* __restrict__ qpos,
                                  const float* __restrict__ Woff,
                                  const float* __restrict__ boff,
                                  const float* __restrict__ Wattn,
                                  const float* __restrict__ battn) {
    extern __shared__ float smem[];
    float* sW = smem;                 // [128][240]
    float* sA = smem + 128 * NCOMB;   // [64][128]

    const int n0  = blockIdx.x * TM;
    const int tid = threadIdx.x;

    for (int idx = tid; idx < 128 * NCOMB; idx += 256) {
        const int k = idx / NCOMB, n = idx - k * NCOMB;
        sW[idx] = (n < OFF_W) ? Woff[k * OFF_W + n] : Wattn[k * ATTN_W + (n - OFF_W)];
    }
    for (int idx = tid; idx < TM * 128; idx += 256) {
        const int g = n0 * CDIM + idx;
        sA[idx] = query[g] + qpos[g];
    }
    __syncthreads();

    const int ty = tid >> 4;   // rows ty*4..ty*4+3
    const int tx = tid & 15;   // cols tx + 16*j

    float acc[4][15];
    #pragma unroll
    for (int i = 0; i < 4; i++)
        #pragma unroll
        for (int j = 0; j < 15; j++) acc[i][j] = 0.f;

    #pragma unroll 4
    for (int k = 0; k < 128; k++) {
        float a[4];
        #pragma unroll
        for (int i = 0; i < 4; i++) a[i] = sA[(ty * 4 + i) * 128 + k];
        #pragma unroll
        for (int j = 0; j < 15; j++) {
            const float w = sW[k * NCOMB + tx + 16 * j];
            #pragma unroll
            for (int i = 0; i < 4; i++) acc[i][j] = fmaf(a[i], w, acc[i][j]);
        }
    }
    __syncthreads();

    #pragma unroll
    for (int i = 0; i < 4; i++)
        #pragma unroll
        for (int j = 0; j < 15; j++)
            sW[(ty * 4 + i) * NCOMB + tx + 16 * j] = acc[i][j];
    __syncthreads();

    for (int idx = tid; idx < TM * OFF_W; idx += 256) {
        const int r = idx / OFF_W, t = idx - r * OFF_W;
        const float v = sW[r * NCOMB + t] + boff[t];
        g_off[(n0 + r) * OFF_W + t] = v * ((t & 1) ? (1.f / 32.f) : (1.f / 88.f));
    }
    {
        const int r = tid >> 2, h = tid & 3;
        float lg[POINTS];
        float mx = -1e30f;
        #pragma unroll
        for (int p = 0; p < POINTS; p++) {
            lg[p] = sW[r * NCOMB + OFF_W + h * POINTS + p] + battn[h * POINTS + p];
            mx = fmaxf(mx, lg[p]);
        }
        float sum = 0.f;
        #pragma unroll
        for (int p = 0; p < POINTS; p++) { lg[p] = __expf(lg[p] - mx); sum += lg[p]; }
        const float inv = 1.f / sum;
        #pragma unroll
        for (int p = 0; p < POINTS; p++)
            g_aw[(n0 + r) * ATTN_W + h * POINTS + p] = lg[p] * inv;
    }
}

// ---------------------------------------------------------------------------
// Kernel B (unchanged R8, col-split): val = value @ Wv + bv -> fp8 e4m3.
// ---------------------------------------------------------------------------
__global__ void k_proj_val_t(const float* __restrict__ value,
                             const float* __restrict__ Wv,
                             const float* __restrict__ bv) {
    extern __shared__ float smem[];
    float* sW = smem;                 // [128][64]
    float* sA = smem + 128 * 64;      // [64][128]

    const int bx  = blockIdx.x;
    const int r0  = (bx >> 1) * TM;   // row tile base
    const int ch  = (bx & 1) * 64;    // column half base
    const int tid = threadIdx.x;

    for (int idx = tid; idx < 128 * 16; idx += 256) {
        const int k = idx >> 4, c4 = idx & 15;
        reinterpret_cast<float4*>(sW)[idx] =
            *reinterpret_cast<const float4*>(&Wv[k * 128 + ch + c4 * 4]);
    }
    for (int idx = tid; idx < TM * 128 / 4; idx += 256)
        reinterpret_cast<float4*>(sA)[idx] =
            reinterpret_cast<const float4*>(value + (size_t)r0 * CDIM)[idx];
    __syncthreads();

    const int ty = tid >> 4;
    const int tx = tid & 15;

    float acc[4][4];
    #pragma unroll
    for (int i = 0; i < 4; i++)
        #pragma unroll
        for (int j = 0; j < 4; j++) acc[i][j] = 0.f;

    #pragma unroll 4
    for (int k = 0; k < 128; k++) {
        float a[4];
        #pragma unroll
        for (int i = 0; i < 4; i++) a[i] = sA[(ty * 4 + i) * 128 + k];
        const float4 w = *reinterpret_cast<const float4*>(&sW[k * 64 + tx * 4]);
        #pragma unroll
        for (int i = 0; i < 4; i++) {
            acc[i][0] = fmaf(a[i], w.x, acc[i][0]);
            acc[i][1] = fmaf(a[i], w.y, acc[i][1]);
            acc[i][2] = fmaf(a[i], w.z, acc[i][2]);
            acc[i][3] = fmaf(a[i], w.w, acc[i][3]);
        }
    }

    const float4 b = *reinterpret_cast<const float4*>(&bv[ch + tx * 4]);
    #pragma unroll
    for (int i = 0; i < 4; i++) {
        const int row = r0 + ty * 4 + i;
        const __nv_fp8x2_storage_t p0 = __nv_cvt_float2_to_fp8x2(
            make_float2(acc[i][0] + b.x, acc[i][1] + b.y), __NV_SATFINITE, __NV_E4M3);
        const __nv_fp8x2_storage_t p1 = __nv_cvt_float2_to_fp8x2(
            make_float2(acc[i][2] + b.z, acc[i][3] + b.w), __NV_SATFINITE, __NV_E4M3);
        const unsigned u = (unsigned)p0 | ((unsigned)p1 << 16);
        *reinterpret_cast<unsigned*>(&g_val[(size_t)row * CDIM + ch + tx * 4]) = u;
    }
}

// ---------------------------------------------------------------------------
// Kernel C: bilinear sampling, fp8 cache, half2 corner accumulation.
// lane = (pt<<3) | (corner<<1) | chgrp; per iteration one LDG.128 (16 fp8),
// 8 decodes + 8 HFMA2. Half2 partials flushed to fp32 per camera.
// Butterfly reduce xor 2,4,8,16 at the end.
// ---------------------------------------------------------------------------
__global__ void k_sample(const float* __restrict__ refpts,   // (S,1,N,4,2)
                         const int* __restrict__ bmask) {    // (S,1,N,4) 4-byte flags
    const int n      = blockIdx.x;
    const int t      = threadIdx.x;
    const int h      = t >> 5;
    const int lane   = t & 31;
    const int chgrp  = lane & 1;         // 16-channel group
    const int corner = (lane >> 1) & 3;  // bilinear corner
    const int dx     = corner & 1, dy = corner >> 1;
    const int pt     = (lane >> 3) & 3;  // point slot; p = 4*i + pt, anchor d = pt

    __shared__ float sOff[OFF_W];
    __shared__ float sAw[ATTN_W];
    __shared__ float sRef[SCAM * 8];
    __shared__ int   sAct[SCAM];
    __shared__ int   sCnt;

    for (int i = t; i < OFF_W; i += 128)  sOff[i] = g_off[n * OFF_W + i];
    for (int i = t; i < ATTN_W; i += 128) sAw[i]  = g_aw[n * ATTN_W + i];
    for (int i = t; i < SCAM * 8; i += 128) {
        const int s = i >> 3, e = i & 7;
        sRef[i] = refpts[((size_t)s * NQ + n) * 8 + e];
    }
    if (t == 0) {
        int cnt = 0;
        #pragma unroll
        for (int s = 0; s < SCAM; s++) {
            const int4 mw = *reinterpret_cast<const int4*>(bmask + ((size_t)s * NQ + n) * DANCH);
            if (mw.x | mw.y | mw.z | mw.w) sAct[cnt++] = s;
        }
        sCnt = cnt;
    }
    __syncthreads();

    // hoist this lane's 5 points (p = 4i + pt): offsets and attention weights
    float ox[5], oy[5], wp[5];
    #pragma unroll
    for (int i = 0; i < 5; i++) {
        const int p = 4 * i + pt;
        ox[i] = sOff[h * 40 + p * 2 + 0];
        oy[i] = sOff[h * 40 + p * 2 + 1];
        wp[i] = sAw[h * POINTS + p];
    }

    float acc[16];
    #pragma unroll
    for (int i = 0; i < 16; i++) acc[i] = 0.f;

    const int cnt = sCnt;
    for (int j = 0; j < cnt; j++) {
        const int s = sAct[j];
        const unsigned char* __restrict__ imgb =
            g_val + (size_t)s * MPIX * CDIM + h * DHEAD + chgrp * 16;
        const float fx = sRef[s * 8 + pt * 2 + 0];
        const float fy = sRef[s * 8 + pt * 2 + 1];

        __half2 hacc[8];
        #pragma unroll
        for (int q = 0; q < 8; q++) hacc[q] = __half2half2(__ushort_as_half(0));

        #pragma unroll
        for (int i = 0; i < 5; i++) {
            const float x = (fx + ox[i]) * 88.f - 0.5f;
            const float y = (fy + oy[i]) * 32.f - 0.5f;
            const float x0f = floorf(x), y0f = floorf(y);
            const float wx = x - x0f, wy = y - y0f;
            const int xx = (int)x0f + dx;
            const int yy = (int)y0f + dy;
            const float wc = (dx ? wx : 1.f - wx) * (dy ? wy : 1.f - wy) * wp[i];

            if ((unsigned)xx < (unsigned)WSZ && (unsigned)yy < (unsigned)HSZ) {
                const uint4 raw = *reinterpret_cast<const uint4*>(imgb + (yy * WSZ + xx) * CDIM);
                const unsigned rw[4] = {raw.x, raw.y, raw.z, raw.w};
                const __half2 wch = __float2half2_rn(wc);
                #pragma unroll
                for (int q = 0; q < 4; q++) {
                    const __half2_raw lor = __nv_cvt_fp8x2_to_halfraw2(
                        (__nv_fp8x2_storage_t)(rw[q] & 0xffffu), __NV_E4M3);
                    const __half2_raw hir = __nv_cvt_fp8x2_to_halfraw2(
                        (__nv_fp8x2_storage_t)(rw[q] >> 16), __NV_E4M3);
                    hacc[q * 2 + 0] = __hfma2(wch, *reinterpret_cast<const __half2*>(&lor),
                                              hacc[q * 2 + 0]);
                    hacc[q * 2 + 1] = __hfma2(wch, *reinterpret_cast<const __half2*>(&hir),
                                              hacc[q * 2 + 1]);
                }
            }
        }

        // flush half2 partials into fp32 accumulators (bounds error growth)
        #pragma unroll
        for (int q = 0; q < 8; q++) {
            const float2 f = __half22float2(hacc[q]);
            acc[q * 2 + 0] += f.x;
            acc[q * 2 + 1] += f.y;
        }
    }

    // reduce over corners (xor 2, 4) and point slots (xor 8, 16)
    #pragma unroll
    for (int m = 2; m <= 16; m <<= 1)
        #pragma unroll
        for (int i = 0; i < 16; i++)
            acc[i] += __shfl_xor_sync(0xffffffffu, acc[i], m);

    if (lane < 2) {
        const float inv = 1.f / fmaxf((float)cnt, 1.0f);
        float* dst = g_slots + (size_t)n * CDIM + h * DHEAD + chgrp * 16;
        #pragma unroll
        for (int q = 0; q < 4; q++) {
            float4 o = make_float4(acc[q * 4 + 0] * inv, acc[q * 4 + 1] * inv,
                                   acc[q * 4 + 2] * inv, acc[q * 4 + 3] * inv);
            *reinterpret_cast<float4*>(dst + q * 4) = o;
        }
    }
}

// ---------------------------------------------------------------------------
// Kernel D (unchanged R8, col-split): out = slots @ Wout + bout + residual.
// ---------------------------------------------------------------------------
__global__ void k_out_t(const float* __restrict__ query,
                        const float* __restrict__ Wout,
                        const float* __restrict__ bout,
                        float* __restrict__ out) {
    extern __shared__ float smem[];
    float* sW = smem;                 // [128][64]
    float* sA = smem + 128 * 64;      // [64][128]

    const int bx  = blockIdx.x;
    const int r0  = (bx >> 1) * TM;
    const int ch  = (bx & 1) * 64;
    const int tid = threadIdx.x;

    for (int idx = tid; idx < 128 * 16; idx += 256) {
        const int k = idx >> 4, c4 = idx & 15;
        reinterpret_cast<float4*>(sW)[idx] =
            *reinterpret_cast<const float4*>(&Wout[k * 128 + ch + c4 * 4]);
    }
    for (int idx = tid; idx < TM * 128 / 4; idx += 256)
        reinterpret_cast<float4*>(sA)[idx] =
            reinterpret_cast<const float4*>(g_slots + (size_t)r0 * CDIM)[idx];
    __syncthreads();

    const int ty = tid >> 4;
    const int tx = tid & 15;

    float acc[4][4];
    #pragma unroll
    for (int i = 0; i < 4; i++)
        #pragma unroll
        for (int j = 0; j < 4; j++) acc[i][j] = 0.f;

    #pragma unroll 4
    for (int k = 0; k < 128; k++) {
        float a[4];
        #pragma unroll
        for (int i = 0; i < 4; i++) a[i] = sA[(ty * 4 + i) * 128 + k];
        const float4 w = *reinterpret_cast<const float4*>(&sW[k * 64 + tx * 4]);
        #pragma unroll
        for (int i = 0; i < 4; i++) {
            acc[i][0] = fmaf(a[i], w.x, acc[i][0]);
            acc[i][1] = fmaf(a[i], w.y, acc[i][1]);
            acc[i][2] = fmaf(a[i], w.z, acc[i][2]);
            acc[i][3] = fmaf(a[i], w.w, acc[i][3]);
        }
    }

    const float4 b = *reinterpret_cast<const float4*>(&bout[ch + tx * 4]);
    #pragma unroll
    for (int i = 0; i < 4; i++) {
        const int row = r0 + ty * 4 + i;
        const float4 q = *reinterpret_cast<const float4*>(&query[row * CDIM + ch + tx * 4]);
        float4 o = make_float4(acc[i][0] + b.x + q.x, acc[i][1] + b.y + q.y,
                               acc[i][2] + b.z + q.z, acc[i][3] + b.w + q.w);
        *reinterpret_cast<float4*>(&out[row * CDIM + ch + tx * 4]) = o;
    }
}

// ---------------------------------------------------------------------------
// Launch. Input order per setup_inputs:
// 0 query, 1 key (unused), 2 value, 3 query_pos, 4 reference_points_cam,
// 5 bev_mask, 6 spatial_shapes, 7 level_start_index, 8 Wv, 9 bv, 10 Woff,
// 11 boff, 12 Wattn, 13 battn, 14 Wout, 15 bout
// ---------------------------------------------------------------------------
extern "C" void kernel_launch(void* const* d_in, const int* in_sizes, int n_in,
                              void* d_out, int out_size) {
    const float* query = (const float*)d_in[0];
    const float* value = (const float*)d_in[2];
    const float* qpos  = (const float*)d_in[3];
    const float* refp  = (const float*)d_in[4];
    const int*   bmask = (const int*)d_in[5];
    const float* Wv    = (const float*)d_in[8];
    const float* bv    = (const float*)d_in[9];
    const float* Woff  = (const float*)d_in[10];
    const float* boff  = (const float*)d_in[11];
    const float* Wattn = (const float*)d_in[12];
    const float* battn = (const float*)d_in[13];
    const float* Wout  = (const float*)d_in[14];
    const float* bout  = (const float*)d_in[15];
    float* out = (float*)d_out;

    const int smemA = (128 * NCOMB + TM * 128) * sizeof(float);   // 155648
    const int smemH = (128 * 64 + TM * 128) * sizeof(float);      // 65536

    cudaFuncSetAttribute(k_proj_off_attn_t, cudaFuncAttributeMaxDynamicSharedMemorySize, smemA);
    cudaFuncSetAttribute(k_proj_val_t,      cudaFuncAttributeMaxDynamicSharedMemorySize, smemH);
    cudaFuncSetAttribute(k_out_t,           cudaFuncAttributeMaxDynamicSharedMemorySize, smemH);

    // Fork: A on the aux stream, B on the main stream; join before sampling.
    cudaEventRecord(g_aux.evFork, 0);
    cudaStreamWaitEvent(g_aux.s, g_aux.evFork, 0);
    k_proj_off_attn_t<<<NQ / TM, 256, smemA, g_aux.s>>>(query, qpos, Woff, boff, Wattn, battn);
    cudaEventRecord(g_aux.evJoin, g_aux.s);

    k_proj_val_t<<<(SCAM * MPIX / TM) * 2, 256, smemH>>>(value, Wv, bv);
    cudaStreamWaitEvent(0, g_aux.evJoin, 0);

    k_sample<<<NQ, CDIM>>>(refp, bmask);
    k_out_t<<<(NQ / TM) * 2, 256, smemH>>>(query, Wout, bout, out);
}

// round 10
// speedup vs baseline: 1.8593x; 1.0772x over previous
#include <cuda_runtime.h>
#include <cuda_bf16.h>
#include <cuda_fp8.h>
#include <cuda_fp16.h>
#include <math.h>

// Problem constants
#define NQ      6400
#define CDIM    128
#define SCAM    6
#define MPIX    2816     // 32*88
#define HEADS   4
#define POINTS  20
#define HSZ     32
#define WSZ     88
#define DHEAD   32
#define DANCH   4
#define OFF_W   160      // HEADS*POINTS*2
#define ATTN_W  80       // HEADS*POINTS
#define NCOMB   240      // OFF_W + ATTN_W

#define TM      64       // rows per GEMM block

// Scratch (device globals -- no allocation allowed)
__device__ float         g_off[NQ * OFF_W];              // sampling offsets, already /norm
__device__ float         g_aw [NQ * ATTN_W];             // softmaxed attention weights
__device__ unsigned char g_val[SCAM * MPIX * CDIM];      // projected value, (s,pix,c) fp8 e4m3
__device__ float         g_slots[NQ * CDIM];             // per-query accumulated slots

// Aux stream for A||B overlap -- created once in a static initializer.
namespace {
struct AuxStream {
    cudaStream_t s;
    cudaEvent_t evFork, evJoin;
    AuxStream() {
        cudaStreamCreateWithFlags(&s, cudaStreamNonBlocking);
        cudaEventCreateWithFlags(&evFork, cudaEventDisableTiming);
        cudaEventCreateWithFlags(&evJoin, cudaEventDisableTiming);
    }
};
AuxStream g_aux;
}

// ---------------------------------------------------------------------------
// Kernel A (unchanged): q = query+query_pos; [offsets | attn logits]
// ---------------------------------------------------------------------------
__global__ void k_proj_off_attn_t(const float* __restrict__ query,
                                  const float* __restrict__ qpos,
                                  const float* __restrict__ Woff,
                                  const float* __restrict__ boff,
                                  const float* __restrict__ Wattn,
                                  const float* __restrict__ battn) {
    extern __shared__ float smem[];
    float* sW = smem;                 // [128][240]
    float* sA = smem + 128 * NCOMB;   // [64][128]

    const int n0  = blockIdx.x * TM;
    const int tid = threadIdx.x;

    for (int idx = tid; idx < 128 * NCOMB; idx += 256) {
        const int k = idx / NCOMB, n = idx - k * NCOMB;
        sW[idx] = (n < OFF_W) ? Woff[k * OFF_W + n] : Wattn[k * ATTN_W + (n - OFF_W)];
    }
    for (int idx = tid; idx < TM * 128; idx += 256) {
        const int g = n0 * CDIM + idx;
        sA[idx] = query[g] + qpos[g];
    }
    __syncthreads();

    const int ty = tid >> 4;   // rows ty*4..ty*4+3
    const int tx = tid & 15;   // cols tx + 16*j

    float acc[4][15];
    #pragma unroll
    for (int i = 0; i < 4; i++)
        #pragma unroll
        for (int j = 0; j < 15; j++) acc[i][j] = 0.f;

    #pragma unroll 4
    for (int k = 0; k < 128; k++) {
        float a[4];
        #pragma unroll
        for (int i = 0; i < 4; i++) a[i] = sA[(ty * 4 + i) * 128 + k];
        #pragma unroll
        for (int j = 0; j < 15; j++) {
            const float w = sW[k * NCOMB + tx + 16 * j];
            #pragma unroll
            for (int i = 0; i < 4; i++) acc[i][j] = fmaf(a[i], w, acc[i][j]);
        }
    }
    __syncthreads();

    #pragma unroll
    for (int i = 0; i < 4; i++)
        #pragma unroll
        for (int j = 0; j < 15; j++)
            sW[(ty * 4 + i) * NCOMB + tx + 16 * j] = acc[i][j];
    __syncthreads();

    for (int idx = tid; idx < TM * OFF_W; idx += 256) {
        const int r = idx / OFF_W, t = idx - r * OFF_W;
        const float v = sW[r * NCOMB + t] + boff[t];
        g_off[(n0 + r) * OFF_W + t] = v * ((t & 1) ? (1.f / 32.f) : (1.f / 88.f));
    }
    {
        const int r = tid >> 2, h = tid & 3;
        float lg[POINTS];
        float mx = -1e30f;
        #pragma unroll
        for (int p = 0; p < POINTS; p++) {
            lg[p] = sW[r * NCOMB + OFF_W + h * POINTS + p] + battn[h * POINTS + p];
            mx = fmaxf(mx, lg[p]);
        }
        float sum = 0.f;
        #pragma unroll
        for (int p = 0; p < POINTS; p++) { lg[p] = __expf(lg[p] - mx); sum += lg[p]; }
        const float inv = 1.f / sum;
        #pragma unroll
        for (int p = 0; p < POINTS; p++)
            g_aw[(n0 + r) * ATTN_W + h * POINTS + p] = lg[p] * inv;
    }
}

// ---------------------------------------------------------------------------
// Kernel B (col-split, float4 a-loads): val = value @ Wv + bv -> fp8 e4m3.
// ---------------------------------------------------------------------------
__global__ void k_proj_val_t(const float* __restrict__ value,
                             const float* __restrict__ Wv,
                             const float* __restrict__ bv) {
    extern __shared__ float smem[];
    float* sW = smem;                 // [128][64]
    float* sA = smem + 128 * 64;      // [64][128]

    const int bx  = blockIdx.x;
    const int r0  = (bx >> 1) * TM;   // row tile base
    const int ch  = (bx & 1) * 64;    // column half base
    const int tid = threadIdx.x;

    for (int idx = tid; idx < 128 * 16; idx += 256) {
        const int k = idx >> 4, c4 = idx & 15;
        reinterpret_cast<float4*>(sW)[idx] =
            *reinterpret_cast<const float4*>(&Wv[k * 128 + ch + c4 * 4]);
    }
    for (int idx = tid; idx < TM * 128 / 4; idx += 256)
        reinterpret_cast<float4*>(sA)[idx] =
            reinterpret_cast<const float4*>(value + (size_t)r0 * CDIM)[idx];
    __syncthreads();

    const int ty = tid >> 4;
    const int tx = tid & 15;

    float acc[4][4];
    #pragma unroll
    for (int i = 0; i < 4; i++)
        #pragma unroll
        for (int j = 0; j < 4; j++) acc[i][j] = 0.f;

    for (int k4 = 0; k4 < 128; k4 += 4) {
        float4 av[4];
        #pragma unroll
        for (int i = 0; i < 4; i++)
            av[i] = *reinterpret_cast<const float4*>(&sA[(ty * 4 + i) * 128 + k4]);
        #pragma unroll
        for (int kk = 0; kk < 4; kk++) {
            const float4 w = *reinterpret_cast<const float4*>(&sW[(k4 + kk) * 64 + tx * 4]);
            #pragma unroll
            for (int i = 0; i < 4; i++) {
                const float a = (&av[i].x)[kk];
                acc[i][0] = fmaf(a, w.x, acc[i][0]);
                acc[i][1] = fmaf(a, w.y, acc[i][1]);
                acc[i][2] = fmaf(a, w.z, acc[i][2]);
                acc[i][3] = fmaf(a, w.w, acc[i][3]);
            }
        }
    }

    const float4 b = *reinterpret_cast<const float4*>(&bv[ch + tx * 4]);
    #pragma unroll
    for (int i = 0; i < 4; i++) {
        const int row = r0 + ty * 4 + i;
        const __nv_fp8x2_storage_t p0 = __nv_cvt_float2_to_fp8x2(
            make_float2(acc[i][0] + b.x, acc[i][1] + b.y), __NV_SATFINITE, __NV_E4M3);
        const __nv_fp8x2_storage_t p1 = __nv_cvt_float2_to_fp8x2(
            make_float2(acc[i][2] + b.z, acc[i][3] + b.w), __NV_SATFINITE, __NV_E4M3);
        const unsigned u = (unsigned)p0 | ((unsigned)p1 << 16);
        *reinterpret_cast<unsigned*>(&g_val[(size_t)row * CDIM + ch + tx * 4]) = u;
    }
}

// ---------------------------------------------------------------------------
// Kernel C: bilinear sampling, branch-free staged gathers, half2 accumulation
// across cameras (single fp32 flush at the end).
// lane = (pt<<3) | (corner<<1) | chgrp. Per camera: compute 5 coord/weight/
// address sets (clamped; wc *= valid preserves zero padding) -> issue 5
// LDG.128 back-to-back (MLP=5) -> decode + HFMA2.
// ---------------------------------------------------------------------------
__global__ void k_sample(const float* __restrict__ refpts,   // (S,1,N,4,2)
                         const int* __restrict__ bmask) {    // (S,1,N,4) 4-byte flags
    const int n      = blockIdx.x;
    const int t      = threadIdx.x;
    const int h      = t >> 5;
    const int lane   = t & 31;
    const int chgrp  = lane & 1;         // 16-channel group
    const int corner = (lane >> 1) & 3;  // bilinear corner
    const int dx     = corner & 1, dy = corner >> 1;
    const int pt     = (lane >> 3) & 3;  // point slot; p = 4*i + pt, anchor d = pt

    __shared__ float sOff[OFF_W];
    __shared__ float sAw[ATTN_W];
    __shared__ float sRef[SCAM * 8];
    __shared__ int   sAct[SCAM];
    __shared__ int   sCnt;

    for (int i = t; i < OFF_W; i += 128)  sOff[i] = g_off[n * OFF_W + i];
    for (int i = t; i < ATTN_W; i += 128) sAw[i]  = g_aw[n * ATTN_W + i];
    for (int i = t; i < SCAM * 8; i += 128) {
        const int s = i >> 3, e = i & 7;
        sRef[i] = refpts[((size_t)s * NQ + n) * 8 + e];
    }
    if (t == 0) {
        int cnt = 0;
        #pragma unroll
        for (int s = 0; s < SCAM; s++) {
            const int4 mw = *reinterpret_cast<const int4*>(bmask + ((size_t)s * NQ + n) * DANCH);
            if (mw.x | mw.y | mw.z | mw.w) sAct[cnt++] = s;
        }
        sCnt = cnt;
    }
    __syncthreads();

    // hoist this lane's 5 points (p = 4i + pt): offsets and attention weights
    float ox[5], oy[5], wp[5];
    #pragma unroll
    for (int i = 0; i < 5; i++) {
        const int p = 4 * i + pt;
        ox[i] = sOff[h * 40 + p * 2 + 0];
        oy[i] = sOff[h * 40 + p * 2 + 1];
        wp[i] = sAw[h * POINTS + p];
    }

    __half2 hacc[8];
    #pragma unroll
    for (int q = 0; q < 8; q++) hacc[q] = __half2half2(__ushort_as_half(0));

    const int cnt = sCnt;
    for (int j = 0; j < cnt; j++) {
        const int s = sAct[j];
        const unsigned char* __restrict__ imgb =
            g_val + (size_t)s * MPIX * CDIM + h * DHEAD + chgrp * 16;
        const float fx = sRef[s * 8 + pt * 2 + 0];
        const float fy = sRef[s * 8 + pt * 2 + 1];

        // stage 1: coords, weights, clamped offsets (branch-free)
        float wcs[5];
        int   offs[5];
        #pragma unroll
        for (int i = 0; i < 5; i++) {
            const float x = (fx + ox[i]) * 88.f - 0.5f;
            const float y = (fy + oy[i]) * 32.f - 0.5f;
            const float x0f = floorf(x), y0f = floorf(y);
            const float wx = x - x0f, wy = y - y0f;
            const int xx = (int)x0f + dx;
            const int yy = (int)y0f + dy;
            const bool valid = ((unsigned)xx < (unsigned)WSZ) & ((unsigned)yy < (unsigned)HSZ);
            const float wc = (dx ? wx : 1.f - wx) * (dy ? wy : 1.f - wy) * wp[i];
            wcs[i] = valid ? wc : 0.f;
            const int xc = min(max(xx, 0), WSZ - 1);
            const int yc = min(max(yy, 0), HSZ - 1);
            offs[i] = (yc * WSZ + xc) * CDIM;
        }

        // stage 2: issue all 5 gathers (MLP = 5)
        uint4 raw[5];
        #pragma unroll
        for (int i = 0; i < 5; i++)
            raw[i] = *reinterpret_cast<const uint4*>(imgb + offs[i]);

        // stage 3: decode + accumulate in half2
        #pragma unroll
        for (int i = 0; i < 5; i++) {
            const __half2 wch = __float2half2_rn(wcs[i]);
            const unsigned rw[4] = {raw[i].x, raw[i].y, raw[i].z, raw[i].w};
            #pragma unroll
            for (int q = 0; q < 4; q++) {
                const __half2_raw lor = __nv_cvt_fp8x2_to_halfraw2(
                    (__nv_fp8x2_storage_t)(rw[q] & 0xffffu), __NV_E4M3);
                const __half2_raw hir = __nv_cvt_fp8x2_to_halfraw2(
                    (__nv_fp8x2_storage_t)(rw[q] >> 16), __NV_E4M3);
                hacc[q * 2 + 0] = __hfma2(wch, *reinterpret_cast<const __half2*>(&lor),
                                          hacc[q * 2 + 0]);
                hacc[q * 2 + 1] = __hfma2(wch, *reinterpret_cast<const __half2*>(&hir),
                                          hacc[q * 2 + 1]);
            }
        }
    }

    // single flush to fp32
    float acc[16];
    #pragma unroll
    for (int q = 0; q < 8; q++) {
        const float2 f = __half22float2(hacc[q]);
        acc[q * 2 + 0] = f.x;
        acc[q * 2 + 1] = f.y;
    }

    // reduce over corners (xor 2, 4) and point slots (xor 8, 16)
    #pragma unroll
    for (int m = 2; m <= 16; m <<= 1)
        #pragma unroll
        for (int i = 0; i < 16; i++)
            acc[i] += __shfl_xor_sync(0xffffffffu, acc[i], m);

    if (lane < 2) {
        const float inv = 1.f / fmaxf((float)cnt, 1.0f);
        float* dst = g_slots + (size_t)n * CDIM + h * DHEAD + chgrp * 16;
        #pragma unroll
        for (int q = 0; q < 4; q++) {
            float4 o = make_float4(acc[q * 4 + 0] * inv, acc[q * 4 + 1] * inv,
                                   acc[q * 4 + 2] * inv, acc[q * 4 + 3] * inv);
            *reinterpret_cast<float4*>(dst + q * 4) = o;
        }
    }
}

// ---------------------------------------------------------------------------
// Kernel D (col-split, float4 a-loads): out = slots @ Wout + bout + residual.
// ---------------------------------------------------------------------------
__global__ void k_out_t(const float* __restrict__ query,
                        const float* __restrict__ Wout,
                        const float* __restrict__ bout,
                        float* __restrict__ out) {
    extern __shared__ float smem[];
    float* sW = smem;                 // [128][64]
    float* sA = smem + 128 * 64;      // [64][128]

    const int bx  = blockIdx.x;
    const int r0  = (bx >> 1) * TM;
    const int ch  = (bx & 1) * 64;
    const int tid = threadIdx.x;

    for (int idx = tid; idx < 128 * 16; idx += 256) {
        const int k = idx >> 4, c4 = idx & 15;
        reinterpret_cast<float4*>(sW)[idx] =
            *reinterpret_cast<const float4*>(&Wout[k * 128 + ch + c4 * 4]);
    }
    for (int idx = tid; idx < TM * 128 / 4; idx += 256)
        reinterpret_cast<float4*>(sA)[idx] =
            reinterpret_cast<const float4*>(g_slots + (size_t)r0 * CDIM)[idx];
    __syncthreads();

    const int ty = tid >> 4;
    const int tx = tid & 15;

    float acc[4][4];
    #pragma unroll
    for (int i = 0; i < 4; i++)
        #pragma unroll
        for (int j = 0; j < 4; j++) acc[i][j] = 0.f;

    for (int k4 = 0; k4 < 128; k4 += 4) {
        float4 av[4];
        #pragma unroll
        for (int i = 0; i < 4; i++)
            av[i] = *reinterpret_cast<const float4*>(&sA[(ty * 4 + i) * 128 + k4]);
        #pragma unroll
        for (int kk = 0; kk < 4; kk++) {
            const float4 w = *reinterpret_cast<const float4*>(&sW[(k4 + kk) * 64 + tx * 4]);
            #pragma unroll
            for (int i = 0; i < 4; i++) {
                const float a = (&av[i].x)[kk];
                acc[i][0] = fmaf(a, w.x, acc[i][0]);
                acc[i][1] = fmaf(a, w.y, acc[i][1]);
                acc[i][2] = fmaf(a, w.z, acc[i][2]);
                acc[i][3] = fmaf(a, w.w, acc[i][3]);
            }
        }
    }

    const float4 b = *reinterpret_cast<const float4*>(&bout[ch + tx * 4]);
    #pragma unroll
    for (int i = 0; i < 4; i++) {
        const int row = r0 + ty * 4 + i;
        const float4 q = *reinterpret_cast<const float4*>(&query[row * CDIM + ch + tx * 4]);
        float4 o = make_float4(acc[i][0] + b.x + q.x, acc[i][1] + b.y + q.y,
                               acc[i][2] + b.z + q.z, acc[i][3] + b.w + q.w);
        *reinterpret_cast<float4*>(&out[row * CDIM + ch + tx * 4]) = o;
    }
}

// ---------------------------------------------------------------------------
// Launch. Input order per setup_inputs:
// 0 query, 1 key (unused), 2 value, 3 query_pos, 4 reference_points_cam,
// 5 bev_mask, 6 spatial_shapes, 7 level_start_index, 8 Wv, 9 bv, 10 Woff,
// 11 boff, 12 Wattn, 13 battn, 14 Wout, 15 bout
// ---------------------------------------------------------------------------
extern "C" void kernel_launch(void* const* d_in, const int* in_sizes, int n_in,
                              void* d_out, int out_size) {
    const float* query = (const float*)d_in[0];
    const float* value = (const float*)d_in[2];
    const float* qpos  = (const float*)d_in[3];
    const float* refp  = (const float*)d_in[4];
    const int*   bmask = (const int*)d_in[5];
    const float* Wv    = (const float*)d_in[8];
    const float* bv    = (const float*)d_in[9];
    const float* Woff  = (const float*)d_in[10];
    const float* boff  = (const float*)d_in[11];
    const float* Wattn = (const float*)d_in[12];
    const float* battn = (const float*)d_in[13];
    const float* Wout  = (const float*)d_in[14];
    const float* bout  = (const float*)d_in[15];
    float* out = (float*)d_out;

    const int smemA = (128 * NCOMB + TM * 128) * sizeof(float);   // 155648
    const int smemH = (128 * 64 + TM * 128) * sizeof(float);      // 65536

    cudaFuncSetAttribute(k_proj_off_attn_t, cudaFuncAttributeMaxDynamicSharedMemorySize, smemA);
    cudaFuncSetAttribute(k_proj_val_t,      cudaFuncAttributeMaxDynamicSharedMemorySize, smemH);
    cudaFuncSetAttribute(k_out_t,           cudaFuncAttributeMaxDynamicSharedMemorySize, smemH);

    // Fork: A on the aux stream, B on the main stream; join before sampling.
    cudaEventRecord(g_aux.evFork, 0);
    cudaStreamWaitEvent(g_aux.s, g_aux.evFork, 0);
    k_proj_off_attn_t<<<NQ / TM, 256, smemA, g_aux.s>>>(query, qpos, Woff, boff, Wattn, battn);
    cudaEventRecord(g_aux.evJoin, g_aux.s);

    k_proj_val_t<<<(SCAM * MPIX / TM) * 2, 256, smemH>>>(value, Wv, bv);
    cudaStreamWaitEvent(0, g_aux.evJoin, 0);

    k_sample<<<NQ, CDIM>>>(refp, bmask);
    k_out_t<<<(NQ / TM) * 2, 256, smemH>>>(query, Wout, bout, out);
}